// round 5
// baseline (speedup 1.0000x reference)
#include <cuda_runtime.h>
#include <cstdint>

#define NB 4
#define NL 1024
#define ND 1024
#define NA 1024
#define NH 16
#define NDH 64
#define NM (NB*NL)          // 4096 token rows
#define FSCALE 0.03125f     // 1/sqrt(1024)
#define LN_EPS 1e-5f

// Scratch: Qh | Kh | Vt | Ctx | O1, each NM*NA floats (80 MB total).
// Qh/Kh head-blocked row-major: [(b*NH+h)*NL + l]*64 + dh
// Vt transposed-head:           [(b*NA + a)*NL + l]
__device__ float g_scratch[(size_t)5 * NM * NA];

// ---------------------------------------------------------------------------
// tf32 helpers
// ---------------------------------------------------------------------------
__device__ __forceinline__ uint32_t f2tf32(float f) {
    uint32_t u;
    asm("cvt.rna.tf32.f32 %0, %1;" : "=r"(u) : "f"(f));
    return u;
}

__device__ __forceinline__ void mma_tf32(float* d, const uint32_t* a, const uint32_t* b) {
    asm volatile(
        "mma.sync.aligned.m16n8k8.row.col.f32.tf32.tf32.f32 "
        "{%0,%1,%2,%3}, {%4,%5,%6,%7}, {%8,%9}, {%0,%1,%2,%3};\n"
        : "+f"(d[0]), "+f"(d[1]), "+f"(d[2]), "+f"(d[3])
        : "r"(a[0]), "r"(a[1]), "r"(a[2]), "r"(a[3]), "r"(b[0]), "r"(b[1]));
}

__device__ __forceinline__ void cp_async16(uint32_t smem, const void* gptr) {
    asm volatile("cp.async.cg.shared.global [%0], [%1], 16;\n" :: "r"(smem), "l"(gptr));
}
__device__ __forceinline__ void cp_commit() { asm volatile("cp.async.commit_group;\n"); }
template<int N>
__device__ __forceinline__ void cp_wait() { asm volatile("cp.async.wait_group %0;\n" :: "n"(N)); }

// ---------------------------------------------------------------------------
// Unified tf32 tensor-core GEMM:  C(4096, 1024) = A @ Bw^T
// op = opBase + blockIdx.z:
//   0: Q fused DUAL K=2048 (x@Wqs^T + qu@Wqo^T), MODE 5 (head-blocked row)
//   1: K = x@Wk^T,  MODE 5
//   2: V = x@Wv^T,  MODE 3 (transposed-head)
//   3: O1 = Ctx@Wo^T + bo, MODE 1 (row-major + bias)
// 3-stage cp.async pipeline, 1 sync/chunk, CTA tile 128x128, 8 warps 64x32.
// ---------------------------------------------------------------------------
#define KC 16
#define SPAD 20
#define BUF_FLT (128 * SPAD)                 // floats per buffer per matrix
#define GEMM_SMEM (3 * BUF_FLT * 2 * 4)      // 61440 bytes

__global__ __launch_bounds__(256)
void gemm_all(int opBase,
              const float* __restrict__ x,   const float* __restrict__ qu,
              const float* __restrict__ Wqs, const float* __restrict__ Wqo,
              const float* __restrict__ Wk,  const float* __restrict__ Wv,
              const float* __restrict__ Wo,  const float* __restrict__ bo,
              const float* __restrict__ Ctx,
              float* __restrict__ Qh, float* __restrict__ Kh,
              float* __restrict__ Vt, float* __restrict__ O1)
{
    extern __shared__ float smf[];
    float* AsB = smf;                 // 3 x [128][SPAD]
    float* BsB = smf + 3 * BUF_FLT;   // 3 x [128][SPAD]

    const int op = opBase + blockIdx.z;
    const float *A0, *A1, *B0, *B1; float* C; int NCH; int mode;
    if (op == 0)      { A0 = x;   A1 = qu; B0 = Wqs; B1 = Wqo; C = Qh; NCH = 128; mode = 5; }
    else if (op == 1) { A0 = x;   A1 = x;  B0 = Wk;  B1 = Wk;  C = Kh; NCH = 64;  mode = 5; }
    else if (op == 2) { A0 = x;   A1 = x;  B0 = Wv;  B1 = Wv;  C = Vt; NCH = 64;  mode = 3; }
    else              { A0 = Ctx; A1 = Ctx; B0 = Wo; B1 = Wo;  C = O1; NCH = 64;  mode = 1; }

    const int tid  = threadIdx.x;
    const int lane = tid & 31;
    const int wid  = tid >> 5;
    const int g    = lane >> 2;
    const int tig  = lane & 3;
    const int wm   = (wid >> 2) << 6;
    const int wn   = (wid & 3) << 5;

    const int rowBase = blockIdx.y << 7;
    const int colBase = blockIdx.x << 7;

    const int r  = tid >> 2;
    const int k4 = (tid & 3) << 2;

    const uint32_t sA0 = __cvta_generic_to_shared(&AsB[r * SPAD + k4]);
    const uint32_t sA1 = __cvta_generic_to_shared(&AsB[(r + 64) * SPAD + k4]);
    const uint32_t sB0 = __cvta_generic_to_shared(&BsB[r * SPAD + k4]);
    const uint32_t sB1 = __cvta_generic_to_shared(&BsB[(r + 64) * SPAD + k4]);
    const uint32_t bufStride = BUF_FLT * 4;

    auto load_chunk = [&](int kt, int buf) {
        const float* Asrc; const float* Bsrc; int kcol;
        if (kt >= 64) { Asrc = A1; Bsrc = B1; kcol = (kt - 64) * KC + k4; }
        else          { Asrc = A0; Bsrc = B0; kcol = kt * KC + k4; }
        const uint32_t off = buf * bufStride;
        cp_async16(sA0 + off, Asrc + (size_t)(rowBase + r)      * ND + kcol);
        cp_async16(sA1 + off, Asrc + (size_t)(rowBase + r + 64) * ND + kcol);
        cp_async16(sB0 + off, Bsrc + (size_t)(colBase + r)      * ND + kcol);
        cp_async16(sB1 + off, Bsrc + (size_t)(colBase + r + 64) * ND + kcol);
        cp_commit();
    };

    float acc[4][4][4];
#pragma unroll
    for (int mt = 0; mt < 4; mt++)
#pragma unroll
        for (int nt = 0; nt < 4; nt++)
#pragma unroll
            for (int e = 0; e < 4; e++) acc[mt][nt][e] = 0.f;

    load_chunk(0, 0);
    load_chunk(1, 1);

    int bufC = 0, bufL = 2;   // compute buffer for kt; load target for kt+2
    for (int kt = 0; kt < NCH; kt++) {
        cp_wait<1>();
        __syncthreads();
        if (kt + 2 < NCH) load_chunk(kt + 2, bufL);

        const float* As = AsB + bufC * BUF_FLT;
        const float* Bs = BsB + bufC * BUF_FLT;
#pragma unroll
        for (int ks = 0; ks < 2; ks++) {
            const int k0 = ks * 8;
            uint32_t afr[4][4], bfr[4][2];
#pragma unroll
            for (int mt = 0; mt < 4; mt++) {
                const int row = wm + mt * 16 + g;
                afr[mt][0] = f2tf32(As[row * SPAD + k0 + tig]);
                afr[mt][1] = f2tf32(As[(row + 8) * SPAD + k0 + tig]);
                afr[mt][2] = f2tf32(As[row * SPAD + k0 + tig + 4]);
                afr[mt][3] = f2tf32(As[(row + 8) * SPAD + k0 + tig + 4]);
            }
#pragma unroll
            for (int nt = 0; nt < 4; nt++) {
                const int col = wn + nt * 8 + g;
                bfr[nt][0] = f2tf32(Bs[col * SPAD + k0 + tig]);
                bfr[nt][1] = f2tf32(Bs[col * SPAD + k0 + tig + 4]);
            }
#pragma unroll
            for (int mt = 0; mt < 4; mt++)
#pragma unroll
                for (int nt = 0; nt < 4; nt++)
                    mma_tf32(acc[mt][nt], afr[mt], bfr[nt]);
        }
        // rotate buffers: (C, C+1, L) -> (C+1, L, C)
        const int t = bufC; bufC = (bufC + 1 == 3) ? 0 : bufC + 1;
        bufL = t;
    }

    // ---------------- epilogue ----------------
    if (mode <= 1) {
#pragma unroll
        for (int mt = 0; mt < 4; mt++) {
            const int row0 = rowBase + wm + mt * 16 + g;
#pragma unroll
            for (int nt = 0; nt < 4; nt++) {
                const int col = colBase + wn + nt * 8 + tig * 2;
                float2 v0 = make_float2(acc[mt][nt][0], acc[mt][nt][1]);
                float2 v1 = make_float2(acc[mt][nt][2], acc[mt][nt][3]);
                if (mode == 1) {
                    float2 bj = *(const float2*)&bo[col];
                    v0.x += bj.x; v0.y += bj.y;
                    v1.x += bj.x; v1.y += bj.y;
                }
                *(float2*)&C[(size_t)row0 * NA + col]       = v0;
                *(float2*)&C[(size_t)(row0 + 8) * NA + col] = v1;
            }
        }
    } else if (mode == 3) {
        const int bb = rowBase >> 10;
        const int lB = (rowBase & (NL - 1));
#pragma unroll
        for (int mt = 0; mt < 4; mt++) {
            const int l0 = lB + wm + mt * 16 + g;
#pragma unroll
            for (int nt = 0; nt < 4; nt++) {
                const int a = colBase + wn + nt * 8 + tig * 2;
                float* cp0 = C + (size_t)(bb * NA + a) * NL;
                float* cp1 = C + (size_t)(bb * NA + a + 1) * NL;
                cp0[l0]     = acc[mt][nt][0];
                cp1[l0]     = acc[mt][nt][1];
                cp0[l0 + 8] = acc[mt][nt][2];
                cp1[l0 + 8] = acc[mt][nt][3];
            }
        }
    } else {  // mode 5: head-blocked row-major
        const int bb = rowBase >> 10;
        const int lB = (rowBase & (NL - 1));
#pragma unroll
        for (int mt = 0; mt < 4; mt++) {
            const int l0 = lB + wm + mt * 16 + g;
#pragma unroll
            for (int nt = 0; nt < 4; nt++) {
                const int a = colBase + wn + nt * 8 + tig * 2;
                const int hh = a >> 6, d = a & 63;
                float* cp = C + ((size_t)(bb * NH + hh) * NL + l0) * NDH + d;
                *(float2*)cp              = make_float2(acc[mt][nt][0], acc[mt][nt][1]);
                *(float2*)(cp + 8 * NDH)  = make_float2(acc[mt][nt][2], acc[mt][nt][3]);
            }
        }
    }
}

// ---------------------------------------------------------------------------
// Tensor-core flash attention (unchanged from round 3 — verified)
// ---------------------------------------------------------------------------
#define ATT_LD 68

__global__ __launch_bounds__(256, 2)
void attn_tc(const float* __restrict__ Qh, const float* __restrict__ Kh,
             const float* __restrict__ Vt, float* __restrict__ Ctx,
             const int* __restrict__ mask)
{
    extern __shared__ uint32_t sm[];
    uint32_t* Ks = sm;                               // [64][ATT_LD]
    uint32_t* Vs = Ks + 64 * ATT_LD;                 // [64][ATT_LD]
    uint32_t* Ps = Vs + 64 * ATT_LD;                 // 8 x [16][ATT_LD]
    float*  msks = (float*)(Ps + 8 * 16 * ATT_LD);   // [1024]

    const int tid  = threadIdx.x;
    const int lane = tid & 31;
    const int wid  = tid >> 5;
    const int g    = lane >> 2;
    const int tig  = lane & 3;
    const int qb   = blockIdx.x;
    const int bh   = blockIdx.y;
    const int b    = bh >> 4;
    const int hoff = (bh & 15) * NDH;

    const float* Qbase = Qh + ((size_t)bh * NL + qb * 128) * NDH;
    const float* Kbase = Kh + (size_t)bh * NL * NDH;
    const float* Vbase = Vt + (size_t)(b * NA + hoff) * NL;
    uint32_t* Pw = Ps + wid * 16 * ATT_LD;

    for (int i = tid; i < NL; i += 256)
        msks[i] = (1.0f - (float)mask[b * NL + i]) * -100000.0f;

    uint32_t aq[8][4];
    {
        const int r0 = wid * 16 + g;
#pragma unroll
        for (int ks = 0; ks < 8; ks++) {
            aq[ks][0] = f2tf32(Qbase[(size_t)r0      * 64 + ks*8 + tig    ] * FSCALE);
            aq[ks][1] = f2tf32(Qbase[(size_t)(r0+8)  * 64 + ks*8 + tig    ] * FSCALE);
            aq[ks][2] = f2tf32(Qbase[(size_t)r0      * 64 + ks*8 + tig + 4] * FSCALE);
            aq[ks][3] = f2tf32(Qbase[(size_t)(r0+8)  * 64 + ks*8 + tig + 4] * FSCALE);
        }
    }

    float oacc[8][4];
#pragma unroll
    for (int nt = 0; nt < 8; nt++)
#pragma unroll
        for (int e = 0; e < 4; e++) oacc[nt][e] = 0.f;
    float mr0 = -1e30f, mr1 = -1e30f, lr0 = 0.f, lr1 = 0.f;

    for (int jb = 0; jb < 16; jb++) {
        __syncthreads();
        {
            int idx = tid;
#pragma unroll
            for (int it = 0; it < 4; it++, idx += 256) {
                const int r = idx >> 4, c4 = (idx & 15) << 2;
                float4 kf = *(const float4*)&Kbase[(size_t)(jb*64 + r) * 64 + c4];
                uint4 ku = make_uint4(f2tf32(kf.x), f2tf32(kf.y), f2tf32(kf.z), f2tf32(kf.w));
                *(uint4*)&Ks[r * ATT_LD + c4] = ku;
                float4 vf = *(const float4*)&Vbase[(size_t)r * NL + jb*64 + c4];
                uint4 vu = make_uint4(f2tf32(vf.x), f2tf32(vf.y), f2tf32(vf.z), f2tf32(vf.w));
                *(uint4*)&Vs[r * ATT_LD + c4] = vu;
            }
        }
        __syncthreads();

        float s[8][4];
#pragma unroll
        for (int nt = 0; nt < 8; nt++) {
            s[nt][0] = s[nt][1] = s[nt][2] = s[nt][3] = 0.f;
#pragma unroll
            for (int ks = 0; ks < 8; ks++) {
                uint32_t bfr[2];
                bfr[0] = Ks[(nt*8 + g) * ATT_LD + ks*8 + tig];
                bfr[1] = Ks[(nt*8 + g) * ATT_LD + ks*8 + tig + 4];
                mma_tf32(s[nt], aq[ks], bfr);
            }
        }

        float rm0 = -1e30f, rm1 = -1e30f;
#pragma unroll
        for (int nt = 0; nt < 8; nt++) {
            float2 mv = *(const float2*)&msks[jb*64 + nt*8 + tig*2];
            s[nt][0] += mv.x; s[nt][1] += mv.y;
            s[nt][2] += mv.x; s[nt][3] += mv.y;
            rm0 = fmaxf(rm0, fmaxf(s[nt][0], s[nt][1]));
            rm1 = fmaxf(rm1, fmaxf(s[nt][2], s[nt][3]));
        }
        rm0 = fmaxf(rm0, __shfl_xor_sync(0xffffffffu, rm0, 1));
        rm0 = fmaxf(rm0, __shfl_xor_sync(0xffffffffu, rm0, 2));
        rm1 = fmaxf(rm1, __shfl_xor_sync(0xffffffffu, rm1, 1));
        rm1 = fmaxf(rm1, __shfl_xor_sync(0xffffffffu, rm1, 2));
        const float mn0 = fmaxf(mr0, rm0), mn1 = fmaxf(mr1, rm1);
        const float c0 = __expf(mr0 - mn0), c1 = __expf(mr1 - mn1);
        mr0 = mn0; mr1 = mn1;
        float rs0 = 0.f, rs1 = 0.f;
#pragma unroll
        for (int nt = 0; nt < 8; nt++) {
            s[nt][0] = __expf(s[nt][0] - mn0); rs0 += s[nt][0];
            s[nt][1] = __expf(s[nt][1] - mn0); rs0 += s[nt][1];
            s[nt][2] = __expf(s[nt][2] - mn1); rs1 += s[nt][2];
            s[nt][3] = __expf(s[nt][3] - mn1); rs1 += s[nt][3];
        }
        rs0 += __shfl_xor_sync(0xffffffffu, rs0, 1);
        rs0 += __shfl_xor_sync(0xffffffffu, rs0, 2);
        rs1 += __shfl_xor_sync(0xffffffffu, rs1, 1);
        rs1 += __shfl_xor_sync(0xffffffffu, rs1, 2);
        lr0 = lr0 * c0 + rs0;
        lr1 = lr1 * c1 + rs1;
#pragma unroll
        for (int nt = 0; nt < 8; nt++) {
            oacc[nt][0] *= c0; oacc[nt][1] *= c0;
            oacc[nt][2] *= c1; oacc[nt][3] *= c1;
        }

        __syncwarp();
#pragma unroll
        for (int nt = 0; nt < 8; nt++) {
            *(uint2*)&Pw[g       * ATT_LD + nt*8 + tig*2] = make_uint2(f2tf32(s[nt][0]), f2tf32(s[nt][1]));
            *(uint2*)&Pw[(g + 8) * ATT_LD + nt*8 + tig*2] = make_uint2(f2tf32(s[nt][2]), f2tf32(s[nt][3]));
        }
        __syncwarp();
        uint32_t ap[8][4];
#pragma unroll
        for (int ks = 0; ks < 8; ks++) {
            ap[ks][0] = Pw[g       * ATT_LD + ks*8 + tig];
            ap[ks][1] = Pw[(g + 8) * ATT_LD + ks*8 + tig];
            ap[ks][2] = Pw[g       * ATT_LD + ks*8 + tig + 4];
            ap[ks][3] = Pw[(g + 8) * ATT_LD + ks*8 + tig + 4];
        }

#pragma unroll
        for (int nt = 0; nt < 8; nt++) {
#pragma unroll
            for (int ks = 0; ks < 8; ks++) {
                uint32_t bfr[2];
                bfr[0] = Vs[(nt*8 + g) * ATT_LD + ks*8 + tig];
                bfr[1] = Vs[(nt*8 + g) * ATT_LD + ks*8 + tig + 4];
                mma_tf32(oacc[nt], ap[ks], bfr);
            }
        }
    }

    const float inv0 = 1.0f / lr0, inv1 = 1.0f / lr1;
    const int q0 = qb * 128 + wid * 16 + g;
    float* Ob = Ctx + ((size_t)(b * NL + q0)) * NA + hoff;
#pragma unroll
    for (int nt = 0; nt < 8; nt++) {
        *(float2*)&Ob[nt*8 + tig*2] =
            make_float2(oacc[nt][0] * inv0, oacc[nt][1] * inv0);
        *(float2*)&Ob[(size_t)8 * NA + nt*8 + tig*2] =
            make_float2(oacc[nt][2] * inv1, oacc[nt][3] * inv1);
    }
}

// ---------------------------------------------------------------------------
// Row LayerNorm over last dim (1024)  (unchanged)
// ---------------------------------------------------------------------------
__global__ __launch_bounds__(256)
void ln_kernel(const float* __restrict__ X, const float* __restrict__ gamma,
               const float* __restrict__ beta, float* __restrict__ out)
{
    __shared__ float ssum[8], ssq[8];
    const int row = blockIdx.x;
    const int tid = threadIdx.x;
    const float* xr = X + (size_t)row * NA;
    float4 v = *(const float4*)&xr[tid*4];
    float s  = v.x + v.y + v.z + v.w;
    float s2 = v.x*v.x + v.y*v.y + v.z*v.z + v.w*v.w;
#pragma unroll
    for (int o = 16; o > 0; o >>= 1) {
        s  += __shfl_xor_sync(0xffffffffu, s,  o);
        s2 += __shfl_xor_sync(0xffffffffu, s2, o);
    }
    if ((tid & 31) == 0) { ssum[tid>>5] = s; ssq[tid>>5] = s2; }
    __syncthreads();
    float ts = 0.f, ts2 = 0.f;
#pragma unroll
    for (int i = 0; i < 8; i++) { ts += ssum[i]; ts2 += ssq[i]; }
    const float mu  = ts * (1.f/1024.f);
    const float var = ts2 * (1.f/1024.f) - mu*mu;
    const float rstd = rsqrtf(var + LN_EPS);
    float4 gm = *(const float4*)&gamma[tid*4];
    float4 be = *(const float4*)&beta[tid*4];
    float4 o;
    o.x = (v.x - mu)*rstd*gm.x + be.x;
    o.y = (v.y - mu)*rstd*gm.y + be.y;
    o.z = (v.z - mu)*rstd*gm.z + be.z;
    o.w = (v.w - mu)*rstd*gm.w + be.w;
    *(float4*)&out[(size_t)row*NA + tid*4] = o;
}

// ---------------------------------------------------------------------------
extern "C" void kernel_launch(void* const* d_in, const int* in_sizes, int n_in,
                              void* d_out, int out_size)
{
    const float* x   = (const float*)d_in[0];
    const float* qu  = (const float*)d_in[1];
    const float* Wk  = (const float*)d_in[2];
    const float* Wqs = (const float*)d_in[3];
    const float* Wqo = (const float*)d_in[4];
    const float* Wv  = (const float*)d_in[5];
    const float* Wo  = (const float*)d_in[6];
    const float* bo  = (const float*)d_in[7];
    const float* gam = (const float*)d_in[8];
    const float* bet = (const float*)d_in[9];
    const int*   msk = (const int*)d_in[10];
    float* out = (float*)d_out;

    float* base = nullptr;
    cudaGetSymbolAddress((void**)&base, g_scratch);
    float* Qh  = base;
    float* Kh  = base + (size_t)1*NM*NA;
    float* Vt  = base + (size_t)2*NM*NA;
    float* Ctx = base + (size_t)3*NM*NA;
    float* O1  = base + (size_t)4*NM*NA;

    static bool attrSet = false;
    if (!attrSet) {
        cudaFuncSetAttribute(gemm_all, cudaFuncAttributeMaxDynamicSharedMemorySize, GEMM_SMEM);
        const int attSmem = (64*ATT_LD + 64*ATT_LD + 8*16*ATT_LD) * 4 + NL * 4;
        cudaFuncSetAttribute(attn_tc, cudaFuncAttributeMaxDynamicSharedMemorySize, attSmem);
        attrSet = true;
    }
    const int attSmem = (64*ATT_LD + 64*ATT_LD + 8*16*ATT_LD) * 4 + NL * 4;  // 73728

    // merged Q(dual)/K/V projection launch
    gemm_all<<<dim3(NA/128, NM/128, 3), 256, GEMM_SMEM>>>(
        0, x, qu, Wqs, Wqo, Wk, Wv, Wo, bo, Ctx, Qh, Kh, Vt, O1);

    attn_tc<<<dim3(NL/128, NB*NH), 256, attSmem>>>(Qh, Kh, Vt, Ctx, msk);

    // output projection + bias
    gemm_all<<<dim3(NA/128, NM/128, 1), 256, GEMM_SMEM>>>(
        3, x, qu, Wqs, Wqo, Wk, Wv, Wo, bo, Ctx, Qh, Kh, Vt, O1);

    ln_kernel<<<NM, 256>>>(O1, gam, bet, out);
}